// round 5
// baseline (speedup 1.0000x reference)
#include <cuda_runtime.h>
#include <cstdint>

#define BATCH 8192
#define DIN   64
#define DMID  1024
#define DOUT  64
#define NK    4

// Scratch (allocation-free rule: __device__ globals)
__device__ float g_bufA[BATCH * DMID];   // 32 MB
__device__ float g_bufB[BATCH * DMID];   // 32 MB
__device__ int   g_perm[BATCH];
__device__ int   g_segOffset[NK + 1];
__device__ int   g_tilePrefix[NK + 1];

// ---------------------------------------------------------------------------
// Prep: detect int32 vs int64 domains, counting-sort rows by domain,
// build segment offsets + padded row-tile prefixes for branch GEMM scheduling.
// ---------------------------------------------------------------------------
__global__ void prep_kernel(const int* __restrict__ dom, int n) {
    __shared__ int cnt[NK];
    __shared__ int ofs[NK];
    __shared__ int is64flag;
    int tid = threadIdx.x;
    if (tid < NK) cnt[tid] = 0;
    if (tid == 0) is64flag = 1;
    __syncthreads();

    // int64 little-endian view => odd int32 words (high halves) all zero.
    for (int i = tid; i < 64; i += blockDim.x)
        if (dom[2 * i + 1] != 0) atomicAnd(&is64flag, 0);
    __syncthreads();
    const int stride = is64flag ? 2 : 1;

    for (int i = tid; i < n; i += blockDim.x)
        atomicAdd(&cnt[dom[i * stride]], 1);
    __syncthreads();

    if (tid == 0) {
        int off = 0, toff = 0;
        for (int k = 0; k < NK; k++) {
            g_segOffset[k]  = off;
            g_tilePrefix[k] = toff;
            ofs[k] = off;
            off  += cnt[k];
            toff += (cnt[k] + 127) >> 7;
        }
        g_segOffset[NK]  = off;
        g_tilePrefix[NK] = toff;
    }
    __syncthreads();

    for (int i = tid; i < n; i += blockDim.x) {
        int d = dom[i * stride];
        int p = atomicAdd(&ofs[d], 1);
        g_perm[p] = i;
    }
}

// ---------------------------------------------------------------------------
// tf32 / cp.async helpers
// ---------------------------------------------------------------------------
__device__ __forceinline__ uint32_t f2tf32(float x) {
    uint32_t r;
    asm("cvt.rna.tf32.f32 %0, %1;" : "=r"(r) : "f"(x));
    return r;
}

__device__ __forceinline__ void split_tf32(float x, uint32_t& hi, uint32_t& lo) {
    hi = f2tf32(x);
    lo = f2tf32(x - __uint_as_float(hi));
}

__device__ __forceinline__ void mma_tf32(float* c, const uint32_t* a, const uint32_t* b) {
    asm volatile(
        "mma.sync.aligned.m16n8k8.row.col.f32.tf32.tf32.f32 "
        "{%0,%1,%2,%3}, {%4,%5,%6,%7}, {%8,%9}, {%0,%1,%2,%3};"
        : "+f"(c[0]), "+f"(c[1]), "+f"(c[2]), "+f"(c[3])
        : "r"(a[0]), "r"(a[1]), "r"(a[2]), "r"(a[3]), "r"(b[0]), "r"(b[1]));
}

__device__ __forceinline__ void cp_async16(uint32_t smem_addr, const void* gptr, int src_bytes) {
    asm volatile("cp.async.ca.shared.global [%0], [%1], 16, %2;"
                 :: "r"(smem_addr), "l"(gptr), "r"(src_bytes));
}
__device__ __forceinline__ void cp_commit() {
    asm volatile("cp.async.commit_group;");
}
template <int N>
__device__ __forceinline__ void cp_wait() {
    asm volatile("cp.async.wait_group %0;" :: "n"(N));
}

// ---------------------------------------------------------------------------
// 3xTF32 tensor-core GEMM, cp.async double-buffered.
// C[M,N] = act(A[M,Kd] * W[Kd,N] + bias)
// CTA tile 128 x TN, K-tile 16, 2 smem stages, 8 warps.
//   TN=128: warp grid 2(m) x 4(n), warp tile 64x32 -> MF=4
//   TN=64 : warp grid 4(m) x 2(n), warp tile 32x32 -> MF=2
// SMEM holds raw fp32 tiles; hi/lo tf32 split happens in registers at
// fragment-load time (3 MMAs per fragment pair).
// A smem [m][k] stride 20; B smem [k][n] stride TN+8 (conflict-free LDS).
// ---------------------------------------------------------------------------
template <int TN, bool RELU, bool BRANCH, bool GATHER, bool SCATTER>
__global__ __launch_bounds__(256) void gemm_tc_kernel(
    const float* __restrict__ A, const float* __restrict__ Wb,
    const float* __restrict__ biasb, float* __restrict__ C,
    int M, int Kd, int N)
{
    constexpr int TM = 128, KT = 16;
    constexpr int AP = 20;        // A smem row stride (floats)
    constexpr int BP = TN + 8;    // B smem row stride (floats)
    constexpr int WMC = (TN == 128) ? 2 : 4;   // warps along M
    constexpr int WMS = TM / WMC;              // rows per warp (64 or 32)
    constexpr int MF  = WMS / 16;              // m16 fragments per warp
    constexpr int NF  = 4;                     // n8 fragments per warp (32 cols)
    constexpr int ACH = TM * KT / 4;           // A float4 chunks per tile (512)
    constexpr int BCH = KT * TN / 4;           // B float4 chunks per tile

    __shared__ float As[2][TM * AP];
    __shared__ float Bs[2][KT * BP];
    __shared__ int   sPerm[TM];

    const int tid  = threadIdx.x;
    const int lane = tid & 31;
    const int warp = tid >> 5;
    const int wm   = warp % WMC;
    const int wn   = warp / WMC;
    const int colBase = blockIdx.x * TN;

    int rowBase, rowEnd, dom = 0;
    if (BRANCH) {
        const int t = blockIdx.y;
        if (t >= g_tilePrefix[NK]) return;   // uniform across CTA
        int k = 0;
#pragma unroll
        for (int j = 1; j < NK; j++)
            if (t >= g_tilePrefix[j]) k = j;
        dom = k;
        rowBase = g_segOffset[k] + (t - g_tilePrefix[k]) * TM;
        rowEnd  = g_segOffset[k + 1];
    } else {
        rowBase = blockIdx.y * TM;
        rowEnd  = M;
    }

    const float* W    = Wb    + (size_t)dom * Kd * N;
    const float* bias = biasb + (size_t)dom * N;

    if (GATHER || SCATTER) {
        for (int i = tid; i < TM; i += 256) {
            int r = rowBase + i;
            sPerm[i] = (r < rowEnd) ? g_perm[r] : -1;
        }
        __syncthreads();
    }

    const uint32_t asBase = (uint32_t)__cvta_generic_to_shared(&As[0][0]);
    const uint32_t bsBase = (uint32_t)__cvta_generic_to_shared(&Bs[0][0]);
    constexpr uint32_t AS_STAGE = TM * AP * 4;
    constexpr uint32_t BS_STAGE = KT * BP * 4;

    // ---- Tile loader: cp.async stage 'st' from k-offset k0 ----
    auto load_tile = [&](int k0, int st) {
        const uint32_t aS = asBase + st * AS_STAGE;
        const uint32_t bS = bsBase + st * BS_STAGE;
#pragma unroll
        for (int c = tid; c < ACH; c += 256) {
            const int m  = c >> 2;
            const int kc = (c & 3) * 4;
            const int r  = rowBase + m;
            const bool ok = (r < rowEnd);
            int gr = ok ? (GATHER ? sPerm[m] : r) : 0;
            cp_async16(aS + (m * AP + kc) * 4,
                       A + (size_t)gr * Kd + k0 + kc, ok ? 16 : 0);
        }
#pragma unroll
        for (int c = tid; c < BCH; c += 256) {
            const int kr = c / (TN / 4);
            const int nc = (c % (TN / 4)) * 4;
            cp_async16(bS + (kr * BP + nc) * 4,
                       W + (size_t)(k0 + kr) * N + colBase + nc, 16);
        }
        cp_commit();
    };

    float acc[MF][NF][4];
#pragma unroll
    for (int i = 0; i < MF; i++)
#pragma unroll
        for (int j = 0; j < NF; j++)
#pragma unroll
            for (int q = 0; q < 4; q++) acc[i][j][q] = 0.f;

    const int r0 = lane >> 2;     // 0..7
    const int kq = lane & 3;      // 0..3
    const int nTiles = Kd / KT;

    load_tile(0, 0);              // prologue

    for (int t = 0; t < nTiles; t++) {
        if (t + 1 < nTiles) load_tile((t + 1) * KT, (t + 1) & 1);
        if (t + 1 < nTiles) cp_wait<1>(); else cp_wait<0>();
        __syncthreads();

        const float* as = &As[t & 1][0];
        const float* bs = &Bs[t & 1][0];

#pragma unroll
        for (int ks = 0; ks < KT; ks += 8) {
            uint32_t ah[MF][4], al[MF][4], bh[NF][2], bl[NF][2];
#pragma unroll
            for (int mf = 0; mf < MF; mf++) {
                const int mb = wm * WMS + mf * 16;
                const int i0 = (mb + r0) * AP + ks + kq;
                const int i1 = (mb + r0 + 8) * AP + ks + kq;
                split_tf32(as[i0],     ah[mf][0], al[mf][0]);
                split_tf32(as[i1],     ah[mf][1], al[mf][1]);
                split_tf32(as[i0 + 4], ah[mf][2], al[mf][2]);
                split_tf32(as[i1 + 4], ah[mf][3], al[mf][3]);
            }
#pragma unroll
            for (int nf = 0; nf < NF; nf++) {
                const int nb = wn * 32 + nf * 8 + r0;
                split_tf32(bs[(ks + kq) * BP + nb],     bh[nf][0], bl[nf][0]);
                split_tf32(bs[(ks + kq + 4) * BP + nb], bh[nf][1], bl[nf][1]);
            }
#pragma unroll
            for (int mf = 0; mf < MF; mf++)
#pragma unroll
                for (int nf = 0; nf < NF; nf++) {
                    mma_tf32(acc[mf][nf], ah[mf], bh[nf]);
                    mma_tf32(acc[mf][nf], ah[mf], bl[nf]);
                    mma_tf32(acc[mf][nf], al[mf], bh[nf]);
                }
        }
        __syncthreads();
    }

    // ---- Epilogue: bias (+ReLU), float2 stores, optional scatter ----
#pragma unroll
    for (int nf = 0; nf < NF; nf++) {
        const int col = colBase + wn * 32 + nf * 8 + (lane & 3) * 2;
        const float b0 = bias[col];
        const float b1 = bias[col + 1];
#pragma unroll
        for (int mf = 0; mf < MF; mf++) {
#pragma unroll
            for (int half = 0; half < 2; half++) {
                const int li = wm * WMS + mf * 16 + (lane >> 2) + half * 8;
                const int r  = rowBase + li;
                if (r < rowEnd) {
                    const int orow = SCATTER ? sPerm[li] : r;
                    float2 v;
                    v.x = acc[mf][nf][half * 2 + 0] + b0;
                    v.y = acc[mf][nf][half * 2 + 1] + b1;
                    if (RELU) {
                        v.x = fmaxf(v.x, 0.f);
                        v.y = fmaxf(v.y, 0.f);
                    }
                    *reinterpret_cast<float2*>(C + (size_t)orow * N + col) = v;
                }
            }
        }
    }
}

// ---------------------------------------------------------------------------
extern "C" void kernel_launch(void* const* d_in, const int* in_sizes, int n_in,
                              void* d_out, int out_size) {
    const float* X   = (const float*)d_in[0];
    const int*   dm  = (const int*)  d_in[1];
    const float* W1  = (const float*)d_in[2];
    const float* b1  = (const float*)d_in[3];
    const float* W2  = (const float*)d_in[4];
    const float* b2  = (const float*)d_in[5];
    const float* W3  = (const float*)d_in[6];
    const float* b3  = (const float*)d_in[7];
    const float* W4  = (const float*)d_in[8];
    const float* b4  = (const float*)d_in[9];
    const float* BW1 = (const float*)d_in[10];
    const float* Bb1 = (const float*)d_in[11];
    const float* BW2 = (const float*)d_in[12];
    const float* Bb2 = (const float*)d_in[13];
    const float* BW3 = (const float*)d_in[14];
    const float* Bb3 = (const float*)d_in[15];
    const float* BW4 = (const float*)d_in[16];
    const float* Bb4 = (const float*)d_in[17];
    float* out = (float*)d_out;

    float *bufA = nullptr, *bufB = nullptr;
    cudaGetSymbolAddress((void**)&bufA, g_bufA);
    cudaGetSymbolAddress((void**)&bufB, g_bufB);

    const dim3 blk(256);
    const dim3 gridMain(DMID / 128, BATCH / 128);          // (8, 64)
    const int  btiles = BATCH / 128 + NK;                  // 68 padded row tiles
    const dim3 gridBr(DMID / 128, btiles);                 // (8, 68)
    const dim3 gridBr4(DOUT / 64, btiles);                 // (1, 68)

    prep_kernel<<<1, 256>>>(dm, BATCH);

    // Shared stack: X -> A -> B -> A -> B   (H4 ends in bufB)
    gemm_tc_kernel<128, true,  false, false, false><<<gridMain, blk>>>(X,    W1, b1, bufA, BATCH, DIN,  DMID);
    gemm_tc_kernel<128, true,  false, false, false><<<gridMain, blk>>>(bufA, W2, b2, bufB, BATCH, DMID, DMID);
    gemm_tc_kernel<128, true,  false, false, false><<<gridMain, blk>>>(bufB, W3, b3, bufA, BATCH, DMID, DMID);
    gemm_tc_kernel<128, true,  false, false, false><<<gridMain, blk>>>(bufA, W4, b4, bufB, BATCH, DMID, DMID);

    // Routed branches (each row through exactly its domain's branch)
    gemm_tc_kernel<128, true,  true,  true,  false><<<gridBr,  blk>>>(bufB, BW1, Bb1, bufA, BATCH, DMID, DMID);
    gemm_tc_kernel<128, true,  true,  false, false><<<gridBr,  blk>>>(bufA, BW2, Bb2, bufB, BATCH, DMID, DMID);
    gemm_tc_kernel<128, true,  true,  false, false><<<gridBr,  blk>>>(bufB, BW3, Bb3, bufA, BATCH, DMID, DMID);
    gemm_tc_kernel<64,  false, true,  false, true ><<<gridBr4, blk>>>(bufA, BW4, Bb4, out,  BATCH, DMID, DOUT);
}